// round 1
// baseline (speedup 1.0000x reference)
#include <cuda_runtime.h>
#include <math.h>

#define Gg   256
#define Nn   512
#define Ee   4096
#define FIN  64
#define FOUT 64
#define Cc   16

// Scratch: xw = x @ W^T  [G, N, FOUT]  (33.5 MB)
__device__ float g_xw[(size_t)Gg * Nn * FOUT];

// ---------------------------------------------------------------------------
// K1: per-graph GEMM  xw[g] = x[g] (512x64) @ W^T (64x64)
// Block: 256 threads, tile = 64 nodes x 64 outputs, 4x4 per thread.
// ---------------------------------------------------------------------------
__global__ __launch_bounds__(256) void k1_xw(const float* __restrict__ x,
                                             const float* __restrict__ w)
{
    __shared__ float Xt[64 * 68];   // Xt[k][n]  (transposed, pad 68 -> float4-aligned, conflict-free reads)
    __shared__ float Wt[64 * 68];   // Wt[k][o]

    const int g     = blockIdx.y;
    const int nbase = blockIdx.x * 64;
    const int t     = threadIdx.x;

    const float* xg = x + ((size_t)g * Nn + nbase) * FIN;

    // Coalesced loads; transposed stores (one-time, cheap vs 1024-FFMA body)
    for (int i = t; i < 4096; i += 256) {
        int r = i >> 6;          // node (for X) / out-row (for W)
        int k = i & 63;
        Xt[k * 68 + r] = xg[r * FIN + k];
        Wt[k * 68 + r] = w[r * FIN + k];
    }
    __syncthreads();

    const int o0 = (t & 15) * 4;
    const int n0 = (t >> 4) * 4;

    float acc[4][4];
    #pragma unroll
    for (int i = 0; i < 4; i++)
        #pragma unroll
        for (int j = 0; j < 4; j++) acc[i][j] = 0.f;

    #pragma unroll 8
    for (int k = 0; k < 64; k++) {
        float4 xv = *(const float4*)&Xt[k * 68 + n0];
        float4 wv = *(const float4*)&Wt[k * 68 + o0];
        float xs[4] = {xv.x, xv.y, xv.z, xv.w};
        float ws[4] = {wv.x, wv.y, wv.z, wv.w};
        #pragma unroll
        for (int i = 0; i < 4; i++)
            #pragma unroll
            for (int j = 0; j < 4; j++)
                acc[i][j] = fmaf(xs[i], ws[j], acc[i][j]);
    }

    float* outp = g_xw + ((size_t)g * Nn + nbase) * FOUT;
    #pragma unroll
    for (int i = 0; i < 4; i++) {
        float4 v = make_float4(acc[i][0], acc[i][1], acc[i][2], acc[i][3]);
        *(float4*)&outp[(size_t)(n0 + i) * FOUT + o0] = v;
    }
}

// ---------------------------------------------------------------------------
// K2: fused per-graph  degree -> rsqrt -> CSR sort -> aggregate(+self-loop)
//     -> bias+ReLU -> classifier dot (16 classes) -> block reduce -> log_softmax
// Block: 512 threads (16 warps), one graph per block. No FP atomics anywhere.
// ---------------------------------------------------------------------------
__global__ __launch_bounds__(512) void k2_fused(const int*   __restrict__ ei,
                                                const float* __restrict__ conv_bias,
                                                const float* __restrict__ lin_w,
                                                const float* __restrict__ lin_b,
                                                float*       __restrict__ out)
{
    __shared__ int   cnt[Nn];
    __shared__ int   sc[Nn];
    __shared__ int   offx[Nn + 1];
    __shared__ int   woff[Nn];
    __shared__ float dinv[Nn];
    __shared__ int   srow[Ee];
    __shared__ float snorm[Ee];
    __shared__ float bias_s[FOUT];
    __shared__ float red[16 * 16];

    const int g   = blockIdx.x;
    const int tid = threadIdx.x;

    const int* rowp = ei + (size_t)g * 2 * Ee;   // sources
    const int* colp = rowp + Ee;                 // targets

    // --- degree count (int shared atomics, spread over 512 bins) ---
    cnt[tid] = 0;
    __syncthreads();
    for (int e = tid; e < Ee; e += 512)
        atomicAdd(&cnt[colp[e]], 1);
    __syncthreads();

    const int myc = cnt[tid];
    dinv[tid] = rsqrtf((float)(myc + 1));        // +1 self-loop; deg >= 1 always
    sc[tid]   = myc;
    __syncthreads();

    // --- Hillis-Steele inclusive scan over 512 bins ---
    for (int s = 1; s < Nn; s <<= 1) {
        int v = (tid >= s) ? sc[tid - s] : 0;
        __syncthreads();
        sc[tid] += v;
        __syncthreads();
    }
    offx[tid + 1] = sc[tid];
    woff[tid]     = sc[tid] - myc;               // exclusive offset = write cursor
    if (tid == 0) offx[0] = 0;
    if (tid < FOUT) bias_s[tid] = conv_bias[tid];
    __syncthreads();

    // --- counting-sort scatter of edges by target (CSR) ---
    for (int e = tid; e < Ee; e += 512) {
        int r = rowp[e], c = colp[e];
        int pos = atomicAdd(&woff[c], 1);
        srow[pos]  = r;
        snorm[pos] = dinv[r] * dinv[c];
    }
    __syncthreads();

    // --- aggregate + bias + relu + classifier partials ---
    const float2* xw2 = (const float2*)(g_xw + (size_t)g * Nn * FOUT);
    const float2* lw2 = (const float2*)lin_w;    // [16][16384] float2
    const int wid  = tid >> 5;
    const int lane = tid & 31;

    float cl[Cc];
    #pragma unroll
    for (int c = 0; c < Cc; c++) cl[c] = 0.f;

    for (int n = wid; n < Nn; n += 16) {
        const float dn = dinv[n];
        float2 a = __ldg(&xw2[n * 32 + lane]);   // self-loop message
        const float sn = dn * dn;
        float ax = a.x * sn, ay = a.y * sn;

        const int b = offx[n], e = offx[n + 1];
        for (int j = b; j < e; j++) {            // warp-uniform loop, broadcast LDS
            int   r  = srow[j];
            float nm = snorm[j];
            float2 v = __ldg(&xw2[r * 32 + lane]);  // 256B coalesced row gather
            ax = fmaf(v.x, nm, ax);
            ay = fmaf(v.y, nm, ay);
        }

        const int f0 = lane * 2;
        ax = fmaxf(ax + bias_s[f0],     0.f);
        ay = fmaxf(ay + bias_s[f0 + 1], 0.f);

        const int base = n * 32 + lane;
        #pragma unroll
        for (int c = 0; c < Cc; c++) {
            float2 wv = __ldg(&lw2[c * (Nn * FOUT / 2) + base]);
            cl[c] = fmaf(ax, wv.x, fmaf(ay, wv.y, cl[c]));
        }
    }

    // --- warp reduce each class, then cross-warp via shared ---
    #pragma unroll
    for (int c = 0; c < Cc; c++) {
        float v = cl[c];
        #pragma unroll
        for (int o = 16; o > 0; o >>= 1)
            v += __shfl_xor_sync(0xffffffffu, v, o);
        cl[c] = v;
    }
    if (lane == 0) {
        #pragma unroll
        for (int c = 0; c < Cc; c++) red[wid * 16 + c] = cl[c];
    }
    __syncthreads();

    // --- final reduce + log_softmax over 16 classes (lanes 0..15 of warp 0) ---
    if (tid < Cc) {
        float s = lin_b[tid];
        #pragma unroll
        for (int w = 0; w < 16; w++) s += red[w * 16 + tid];

        float m = s;
        #pragma unroll
        for (int o = 8; o > 0; o >>= 1)
            m = fmaxf(m, __shfl_xor_sync(0xffffu, m, o, 16));
        float ex = expf(s - m);
        float se = ex;
        #pragma unroll
        for (int o = 8; o > 0; o >>= 1)
            se += __shfl_xor_sync(0xffffu, se, o, 16);
        out[g * Cc + tid] = (s - m) - logf(se);
    }
}

// ---------------------------------------------------------------------------
extern "C" void kernel_launch(void* const* d_in, const int* in_sizes, int n_in,
                              void* d_out, int out_size)
{
    const float* x  = (const float*)d_in[0];   // [G, N, F_IN]
    const int*   ei = (const int*)  d_in[1];   // [G, 2, E]
    const float* cw = (const float*)d_in[2];   // [F_OUT, F_IN]
    const float* cb = (const float*)d_in[3];   // [F_OUT]
    const float* lw = (const float*)d_in[4];   // [C, N*F_OUT]
    const float* lb = (const float*)d_in[5];   // [C]
    float* out = (float*)d_out;                // [G, C]

    dim3 g1(Nn / 64, Gg);
    k1_xw<<<g1, 256>>>(x, cw);
    k2_fused<<<Gg, 512>>>(ei, cb, lw, lb, out);
}